// round 1
// baseline (speedup 1.0000x reference)
#include <cuda_runtime.h>
#include <math.h>

#define BB 2
#define NN 64
#define EE 256
#define HH 8
#define DD 32
#define FF 512
#define MR 8192            // BB*NN*NN
#define LNEPS 1e-5f

// ---------------- scratch (static device globals; no allocation) ----------------
__device__ float g_q [MR*EE];
__device__ float g_k [MR*EE];
__device__ float g_v1[MR*EE];
__device__ float g_v2[MR*EE];
__device__ float g_att[BB*HH*NN*NN*NN];   // [b,h,l,i,j]
__device__ float g_ao[MR*EE];             // attention einsum out, row=(b,i,j), col=(h,d)
__device__ float g_h [MR*EE];             // post first LayerNorm
__device__ float g_m1[MR*FF];             // relu(h@W1+b1)

// ---------------- packed fp32x2 FMA (full-rate fp32 on sm_100a) ----------------
__device__ __forceinline__ void fma2(float2& c, const float2 a, const float2 b) {
    asm("fma.rn.f32x2 %0, %1, %2, %0;"
        : "+l"(reinterpret_cast<unsigned long long&>(c))
        : "l"(reinterpret_cast<const unsigned long long&>(a)),
          "l"(reinterpret_cast<const unsigned long long&>(b)));
}
__device__ __forceinline__ float2 dup2(float x) { float2 r; r.x = x; r.y = x; return r; }

// =====================================================================
// GEMM A: C[8192 x LDB-tile] = A[8192 x KDIM] @ B[KDIM x LDB]
// tile 128x64, 256 threads, micro 8x4 (rows packed in f32x2 pairs)
// =====================================================================
template<int KDIM, int LDB, bool RELU_BIAS>
__global__ __launch_bounds__(256, 2)
void gemmA(const float* __restrict__ A, const float* __restrict__ Bw,
           const float* __restrict__ bias, float* __restrict__ C) {
    __shared__ float As[16][128];
    __shared__ float Bs[16][64];
    const int mBase = blockIdx.x * 128;
    const int nBase = blockIdx.y * 64;
    const int tid = threadIdx.x;
    const int ty = tid >> 4, tx = tid & 15;

    float2 acc[4][4];
    #pragma unroll
    for (int i = 0; i < 4; i++)
        #pragma unroll
        for (int j = 0; j < 4; j++) acc[i][j] = make_float2(0.f, 0.f);

    const int lm = tid >> 1;           // 0..127
    const int lk = (tid & 1) * 8;      // 0 or 8
    const int bk = tid >> 4;           // 0..15
    const int bn = (tid & 15) * 4;

    for (int k0 = 0; k0 < KDIM; k0 += 16) {
        const float* ap = &A[(mBase + lm) * KDIM + k0 + lk];
        float4 a0 = *(const float4*)ap;
        float4 a1 = *(const float4*)(ap + 4);
        As[lk+0][lm] = a0.x; As[lk+1][lm] = a0.y; As[lk+2][lm] = a0.z; As[lk+3][lm] = a0.w;
        As[lk+4][lm] = a1.x; As[lk+5][lm] = a1.y; As[lk+6][lm] = a1.z; As[lk+7][lm] = a1.w;
        *(float4*)&Bs[bk][bn] = *(const float4*)&Bw[(k0 + bk) * LDB + nBase + bn];
        __syncthreads();
        #pragma unroll
        for (int k = 0; k < 16; k++) {
            float4 av0 = *(const float4*)&As[k][ty * 8];
            float4 av1 = *(const float4*)&As[k][ty * 8 + 4];
            float2 a2[4];
            a2[0] = make_float2(av0.x, av0.y); a2[1] = make_float2(av0.z, av0.w);
            a2[2] = make_float2(av1.x, av1.y); a2[3] = make_float2(av1.z, av1.w);
            float4 bv = *(const float4*)&Bs[k][tx * 4];
            float2 bd[4] = { dup2(bv.x), dup2(bv.y), dup2(bv.z), dup2(bv.w) };
            #pragma unroll
            for (int i = 0; i < 4; i++)
                #pragma unroll
                for (int j = 0; j < 4; j++) fma2(acc[i][j], a2[i], bd[j]);
        }
        __syncthreads();
    }

    float4 bsv = make_float4(0.f, 0.f, 0.f, 0.f);
    if (RELU_BIAS) bsv = *(const float4*)&bias[nBase + tx * 4];
    #pragma unroll
    for (int i = 0; i < 4; i++) {
        #pragma unroll
        for (int s = 0; s < 2; s++) {
            int row = mBase + ty * 8 + 2 * i + s;
            float4 v;
            v.x = s ? acc[i][0].y : acc[i][0].x;
            v.y = s ? acc[i][1].y : acc[i][1].x;
            v.z = s ? acc[i][2].y : acc[i][2].x;
            v.w = s ? acc[i][3].y : acc[i][3].x;
            if (RELU_BIAS) {
                v.x = fmaxf(v.x + bsv.x, 0.f);
                v.y = fmaxf(v.y + bsv.y, 0.f);
                v.z = fmaxf(v.z + bsv.z, 0.f);
                v.w = fmaxf(v.w + bsv.w, 0.f);
            }
            *(float4*)&C[row * LDB + nBase + tx * 4] = v;
        }
    }
}

// =====================================================================
// GEMM B: full-row (256-col) tiles + residual + LayerNorm epilogue
// tile 32x256, 256 threads, micro 4x8 (cols packed; col split {tx*4, 128+tx*4})
// MODE 0: out = LN(A@B + res)            (res = x_in, LN=ln_agg)  -> g_h
// MODE 1: out = LN(A@B + bias + res)     (res = g_h,  LN=ln_out)  -> d_out
// =====================================================================
template<int KDIM, int MODE>
__global__ __launch_bounds__(256)
void gemmB(const float* __restrict__ A, const float* __restrict__ Bw,
           const float* __restrict__ res, const float* __restrict__ bias,
           const float* __restrict__ lg, const float* __restrict__ lb,
           float* __restrict__ C) {
    __shared__ float As[16][32];
    __shared__ float Bs[16][256];
    const int mBase = blockIdx.x * 32;
    const int tid = threadIdx.x;
    const int ty = tid >> 5, tx = tid & 31;   // warp == one ty (4 rows)

    float2 acc[4][4];
    #pragma unroll
    for (int i = 0; i < 4; i++)
        #pragma unroll
        for (int j = 0; j < 4; j++) acc[i][j] = make_float2(0.f, 0.f);

    const int lm = tid >> 3;            // 0..31
    const int lk = (tid & 7) * 2;       // 0..14
    const int bk = tid >> 4;            // 0..15
    const int bn = (tid & 15) * 16;

    for (int k0 = 0; k0 < KDIM; k0 += 16) {
        float2 av = *(const float2*)&A[(mBase + lm) * KDIM + k0 + lk];
        As[lk][lm] = av.x; As[lk + 1][lm] = av.y;
        #pragma unroll
        for (int c = 0; c < 4; c++)
            *(float4*)&Bs[bk][bn + c * 4] = *(const float4*)&Bw[(k0 + bk) * 256 + bn + c * 4];
        __syncthreads();
        #pragma unroll
        for (int k = 0; k < 16; k++) {
            float4 av4 = *(const float4*)&As[k][ty * 4];
            float2 ad[4] = { dup2(av4.x), dup2(av4.y), dup2(av4.z), dup2(av4.w) };
            float4 b0 = *(const float4*)&Bs[k][tx * 4];
            float4 b1 = *(const float4*)&Bs[k][128 + tx * 4];
            float2 bp[4];
            bp[0] = make_float2(b0.x, b0.y); bp[1] = make_float2(b0.z, b0.w);
            bp[2] = make_float2(b1.x, b1.y); bp[3] = make_float2(b1.z, b1.w);
            #pragma unroll
            for (int i = 0; i < 4; i++)
                #pragma unroll
                for (int j = 0; j < 4; j++) fma2(acc[i][j], ad[i], bp[j]);
        }
        __syncthreads();
    }

    // epilogue: unpack, add residual (+bias), LayerNorm per row, store
    float4 ba = make_float4(0.f, 0.f, 0.f, 0.f), bb4 = ba;
    if (MODE == 1) {
        ba  = *(const float4*)&bias[tx * 4];
        bb4 = *(const float4*)&bias[128 + tx * 4];
    }
    const float4 ga  = *(const float4*)&lg[tx * 4];
    const float4 gb  = *(const float4*)&lg[128 + tx * 4];
    const float4 oa  = *(const float4*)&lb[tx * 4];
    const float4 ob  = *(const float4*)&lb[128 + tx * 4];

    #pragma unroll
    for (int i = 0; i < 4; i++) {
        const int row = mBase + ty * 4 + i;
        float4 r0 = *(const float4*)&res[row * 256 + tx * 4];
        float4 r1 = *(const float4*)&res[row * 256 + 128 + tx * 4];
        float v[8];
        v[0] = acc[i][0].x + r0.x; v[1] = acc[i][0].y + r0.y;
        v[2] = acc[i][1].x + r0.z; v[3] = acc[i][1].y + r0.w;
        v[4] = acc[i][2].x + r1.x; v[5] = acc[i][2].y + r1.y;
        v[6] = acc[i][3].x + r1.z; v[7] = acc[i][3].y + r1.w;
        if (MODE == 1) {
            v[0] += ba.x;  v[1] += ba.y;  v[2] += ba.z;  v[3] += ba.w;
            v[4] += bb4.x; v[5] += bb4.y; v[6] += bb4.z; v[7] += bb4.w;
        }
        float s = 0.f, q = 0.f;
        #pragma unroll
        for (int c = 0; c < 8; c++) { s += v[c]; q += v[c] * v[c]; }
        #pragma unroll
        for (int o = 16; o > 0; o >>= 1) {
            s += __shfl_xor_sync(0xffffffffu, s, o);
            q += __shfl_xor_sync(0xffffffffu, q, o);
        }
        const float mean = s * (1.f / 256.f);
        const float var  = q * (1.f / 256.f) - mean * mean;
        const float rstd = rsqrtf(var + LNEPS);
        float4 o0, o1;
        o0.x = (v[0] - mean) * rstd * ga.x + oa.x;
        o0.y = (v[1] - mean) * rstd * ga.y + oa.y;
        o0.z = (v[2] - mean) * rstd * ga.z + oa.z;
        o0.w = (v[3] - mean) * rstd * ga.w + oa.w;
        o1.x = (v[4] - mean) * rstd * gb.x + ob.x;
        o1.y = (v[5] - mean) * rstd * gb.y + ob.y;
        o1.z = (v[6] - mean) * rstd * gb.z + ob.z;
        o1.w = (v[7] - mean) * rstd * gb.w + ob.w;
        *(float4*)&C[row * 256 + tx * 4] = o0;
        *(float4*)&C[row * 256 + 128 + tx * 4] = o1;
    }
}

// =====================================================================
// scores: S[b,h,l,i,j] = (1/sqrt(32)) * sum_d q[b,i,l,h,d] * k[b,l,j,h,d]
// one block per (b,h,l): 64x64x32 GEMM
// =====================================================================
__global__ __launch_bounds__(256)
void scores_kernel() {
    __shared__ float Qs[32][64];
    __shared__ float Ks[32][64];
    const int bid = blockIdx.x;
    const int l = bid & 63, h = (bid >> 6) & 7, b = bid >> 9;
    const int tid = threadIdx.x;

    const int r  = tid >> 2;          // 0..63
    const int dg = (tid & 3) * 8;
    {
        const float* qp = &g_q[(((b * NN + r) * NN + l) * EE) + h * DD + dg];
        float4 q0 = *(const float4*)qp; float4 q1 = *(const float4*)(qp + 4);
        Qs[dg+0][r] = q0.x; Qs[dg+1][r] = q0.y; Qs[dg+2][r] = q0.z; Qs[dg+3][r] = q0.w;
        Qs[dg+4][r] = q1.x; Qs[dg+5][r] = q1.y; Qs[dg+6][r] = q1.z; Qs[dg+7][r] = q1.w;
        const float* kp = &g_k[(((b * NN + l) * NN + r) * EE) + h * DD + dg];
        float4 k0 = *(const float4*)kp; float4 k1 = *(const float4*)(kp + 4);
        Ks[dg+0][r] = k0.x; Ks[dg+1][r] = k0.y; Ks[dg+2][r] = k0.z; Ks[dg+3][r] = k0.w;
        Ks[dg+4][r] = k1.x; Ks[dg+5][r] = k1.y; Ks[dg+6][r] = k1.z; Ks[dg+7][r] = k1.w;
    }
    __syncthreads();

    const int ty = tid >> 4, tx = tid & 15;
    float acc[4][4];
    #pragma unroll
    for (int i = 0; i < 4; i++)
        #pragma unroll
        for (int j = 0; j < 4; j++) acc[i][j] = 0.f;

    #pragma unroll
    for (int d = 0; d < 32; d++) {
        float4 a  = *(const float4*)&Qs[d][ty * 4];
        float4 bv = *(const float4*)&Ks[d][tx * 4];
        float aa[4] = { a.x, a.y, a.z, a.w };
        float bbv[4] = { bv.x, bv.y, bv.z, bv.w };
        #pragma unroll
        for (int i = 0; i < 4; i++)
            #pragma unroll
            for (int j = 0; j < 4; j++) acc[i][j] = fmaf(aa[i], bbv[j], acc[i][j]);
    }
    const float sc = 0.17677669529663687f;  // 1/sqrt(32)
    float* sp = &g_att[((b * HH + h) * NN + l) * NN * NN];
    #pragma unroll
    for (int i = 0; i < 4; i++) {
        float4 v = make_float4(acc[i][0] * sc, acc[i][1] * sc, acc[i][2] * sc, acc[i][3] * sc);
        *(float4*)&sp[(ty * 4 + i) * 64 + tx * 4] = v;
    }
}

// =====================================================================
// softmax over l (axis 2): one thread per (b,h,i,j)
// =====================================================================
__global__ __launch_bounds__(256)
void softmax_kernel() {
    const int t = blockIdx.x * 256 + threadIdx.x;   // 65536 total
    const int j = t & 63, i = (t >> 6) & 63, bh = t >> 12;
    float* base = &g_att[bh * 262144 + i * 64 + j];
    float r[64];
    float mx = -1e30f;
    #pragma unroll
    for (int l = 0; l < 64; l++) { r[l] = base[l * 4096]; mx = fmaxf(mx, r[l]); }
    float s = 0.f;
    #pragma unroll
    for (int l = 0; l < 64; l++) { r[l] = expf(r[l] - mx); s += r[l]; }
    const float inv = 1.f / s;
    #pragma unroll
    for (int l = 0; l < 64; l++) base[l * 4096] = r[l] * inv;
}

// =====================================================================
// aggregate: out[b,i,j,h,d] = sum_l att[b,h,l,i,j]*v1[b,i,l,h,d]*v2[b,l,j,h,d]
// one block per (b,h, i-tile of 8); thread = (i', d); 64 j-accumulators
// =====================================================================
__global__ __launch_bounds__(256)
void aggregate_kernel() {
    __shared__ float att_s[8][64];
    __shared__ float v2s[64][36];   // padded to break store bank conflicts
    const int bid = blockIdx.x;     // 128 blocks
    const int it = bid & 7, h = (bid >> 3) & 7, b = bid >> 6;
    const int iBase = it * 8;
    const int tid = threadIdx.x;
    const int ip = tid >> 5, d = tid & 31;

    float acc[64];
    #pragma unroll
    for (int j = 0; j < 64; j++) acc[j] = 0.f;

    const int aj = (tid * 2) & 63, ai = (tid * 2) >> 6;
    const int vj = tid >> 2, vdg = (tid & 3) * 8;

    for (int l = 0; l < 64; l++) {
        const float v1v = g_v1[(((b * NN + iBase + ip) * NN + l) * EE) + h * DD + d];
        *(float2*)&att_s[ai][aj] =
            *(const float2*)&g_att[(b * HH + h) * 262144 + l * 4096 + (iBase + ai) * 64 + aj];
        const float* vp = &g_v2[(((b * NN + l) * NN + vj) * EE) + h * DD + vdg];
        *(float4*)&v2s[vj][vdg]     = *(const float4*)vp;
        *(float4*)&v2s[vj][vdg + 4] = *(const float4*)(vp + 4);
        __syncthreads();
        #pragma unroll
        for (int j4 = 0; j4 < 64; j4 += 4) {
            float4 a = *(const float4*)&att_s[ip][j4];
            acc[j4+0] = fmaf(a.x * v1v, v2s[j4+0][d], acc[j4+0]);
            acc[j4+1] = fmaf(a.y * v1v, v2s[j4+1][d], acc[j4+1]);
            acc[j4+2] = fmaf(a.z * v1v, v2s[j4+2][d], acc[j4+2]);
            acc[j4+3] = fmaf(a.w * v1v, v2s[j4+3][d], acc[j4+3]);
        }
        __syncthreads();
    }
    #pragma unroll
    for (int j = 0; j < 64; j++)
        g_ao[(((b * NN + iBase + ip) * NN + j) * EE) + h * DD + d] = acc[j];
}

// =====================================================================
extern "C" void kernel_launch(void* const* d_in, const int* in_sizes, int n_in,
                              void* d_out, int out_size) {
    const float* x    = (const float*)d_in[0];
    const float* Wq   = (const float*)d_in[1];
    const float* Wk   = (const float*)d_in[2];
    const float* Wv1  = (const float*)d_in[3];
    const float* Wv2  = (const float*)d_in[4];
    const float* Wo   = (const float*)d_in[5];
    const float* lag  = (const float*)d_in[6];
    const float* lab  = (const float*)d_in[7];
    const float* W1   = (const float*)d_in[8];
    const float* b1   = (const float*)d_in[9];
    const float* W2   = (const float*)d_in[10];
    const float* b2   = (const float*)d_in[11];
    const float* log_ = (const float*)d_in[12];
    const float* lob  = (const float*)d_in[13];

    float *pq, *pk, *pv1, *pv2, *pao, *ph, *pm1;
    cudaGetSymbolAddress((void**)&pq,  g_q);
    cudaGetSymbolAddress((void**)&pk,  g_k);
    cudaGetSymbolAddress((void**)&pv1, g_v1);
    cudaGetSymbolAddress((void**)&pv2, g_v2);
    cudaGetSymbolAddress((void**)&pao, g_ao);
    cudaGetSymbolAddress((void**)&ph,  g_h);
    cudaGetSymbolAddress((void**)&pm1, g_m1);

    dim3 gQ(64, 4);
    gemmA<256, 256, false><<<gQ, 256>>>(x, Wq,  nullptr, pq);
    gemmA<256, 256, false><<<gQ, 256>>>(x, Wk,  nullptr, pk);
    gemmA<256, 256, false><<<gQ, 256>>>(x, Wv1, nullptr, pv1);
    gemmA<256, 256, false><<<gQ, 256>>>(x, Wv2, nullptr, pv2);

    scores_kernel<<<1024, 256>>>();
    softmax_kernel<<<256, 256>>>();
    aggregate_kernel<<<128, 256>>>();

    gemmB<256, 0><<<256, 256>>>(pao, Wo, x, nullptr, lag, lab, ph);
    gemmA<256, 512, true><<<dim3(64, 8), 256>>>(ph, W1, b1, pm1);
    gemmB<512, 1><<<256, 256>>>(pm1, W2, ph, b2, log_, lob, (float*)d_out);
}

// round 2
// speedup vs baseline: 1.0003x; 1.0003x over previous
#include <cuda_runtime.h>
#include <math.h>

#define BB 2
#define NN 64
#define EE 256
#define HH 8
#define DD 32
#define FF 512
#define MR 8192            // BB*NN*NN
#define LNEPS 1e-5f

// ---------------- scratch (static device globals; no allocation) ----------------
__device__ float g_q [MR*EE];
__device__ float g_k [MR*EE];
__device__ float g_v1[MR*EE];
__device__ float g_v2[MR*EE];
__device__ float g_att[BB*HH*NN*NN*NN];   // [b,h,l,i,j]
__device__ float g_ao[MR*EE];             // attention einsum out, row=(b,i,j), col=(h,d)
__device__ float g_h [MR*EE];             // post first LayerNorm
__device__ float g_m1[MR*FF];             // relu(h@W1+b1)

// ---------------- packed fp32x2 FMA (full-rate fp32 on sm_100a) ----------------
__device__ __forceinline__ void fma2(float2& c, const float2 a, const float2 b) {
    asm("fma.rn.f32x2 %0, %1, %2, %0;"
        : "+l"(reinterpret_cast<unsigned long long&>(c))
        : "l"(reinterpret_cast<const unsigned long long&>(a)),
          "l"(reinterpret_cast<const unsigned long long&>(b)));
}
__device__ __forceinline__ float2 dup2(float x) { float2 r; r.x = x; r.y = x; return r; }

// =====================================================================
// GEMM A: C[8192 x LDB-tile] = A[8192 x KDIM] @ B[KDIM x LDB]
// tile 128x64, 256 threads, micro 8x4 (rows packed in f32x2 pairs)
// =====================================================================
template<int KDIM, int LDB, bool RELU_BIAS>
__global__ __launch_bounds__(256, 2)
void gemmA(const float* __restrict__ A, const float* __restrict__ Bw,
           const float* __restrict__ bias, float* __restrict__ C) {
    __shared__ float As[16][128];
    __shared__ float Bs[16][64];
    const int mBase = blockIdx.x * 128;
    const int nBase = blockIdx.y * 64;
    const int tid = threadIdx.x;
    const int ty = tid >> 4, tx = tid & 15;

    float2 acc[4][4];
    #pragma unroll
    for (int i = 0; i < 4; i++)
        #pragma unroll
        for (int j = 0; j < 4; j++) acc[i][j] = make_float2(0.f, 0.f);

    const int lm = tid >> 1;           // 0..127
    const int lk = (tid & 1) * 8;      // 0 or 8
    const int bk = tid >> 4;           // 0..15
    const int bn = (tid & 15) * 4;

    for (int k0 = 0; k0 < KDIM; k0 += 16) {
        const float* ap = &A[(mBase + lm) * KDIM + k0 + lk];
        float4 a0 = *(const float4*)ap;
        float4 a1 = *(const float4*)(ap + 4);
        As[lk+0][lm] = a0.x; As[lk+1][lm] = a0.y; As[lk+2][lm] = a0.z; As[lk+3][lm] = a0.w;
        As[lk+4][lm] = a1.x; As[lk+5][lm] = a1.y; As[lk+6][lm] = a1.z; As[lk+7][lm] = a1.w;
        *(float4*)&Bs[bk][bn] = *(const float4*)&Bw[(k0 + bk) * LDB + nBase + bn];
        __syncthreads();
        #pragma unroll
        for (int k = 0; k < 16; k++) {
            float4 av0 = *(const float4*)&As[k][ty * 8];
            float4 av1 = *(const float4*)&As[k][ty * 8 + 4];
            float2 a2[4];
            a2[0] = make_float2(av0.x, av0.y); a2[1] = make_float2(av0.z, av0.w);
            a2[2] = make_float2(av1.x, av1.y); a2[3] = make_float2(av1.z, av1.w);
            float4 bv = *(const float4*)&Bs[k][tx * 4];
            float2 bd[4] = { dup2(bv.x), dup2(bv.y), dup2(bv.z), dup2(bv.w) };
            #pragma unroll
            for (int i = 0; i < 4; i++)
                #pragma unroll
                for (int j = 0; j < 4; j++) fma2(acc[i][j], a2[i], bd[j]);
        }
        __syncthreads();
    }

    float4 bsv = make_float4(0.f, 0.f, 0.f, 0.f);
    if (RELU_BIAS) bsv = *(const float4*)&bias[nBase + tx * 4];
    #pragma unroll
    for (int i = 0; i < 4; i++) {
        #pragma unroll
        for (int s = 0; s < 2; s++) {
            int row = mBase + ty * 8 + 2 * i + s;
            float4 v;
            v.x = s ? acc[i][0].y : acc[i][0].x;
            v.y = s ? acc[i][1].y : acc[i][1].x;
            v.z = s ? acc[i][2].y : acc[i][2].x;
            v.w = s ? acc[i][3].y : acc[i][3].x;
            if (RELU_BIAS) {
                v.x = fmaxf(v.x + bsv.x, 0.f);
                v.y = fmaxf(v.y + bsv.y, 0.f);
                v.z = fmaxf(v.z + bsv.z, 0.f);
                v.w = fmaxf(v.w + bsv.w, 0.f);
            }
            *(float4*)&C[row * LDB + nBase + tx * 4] = v;
        }
    }
}

// =====================================================================
// GEMM B: full-row (256-col) tiles + residual + LayerNorm epilogue
// tile 32x256, 256 threads, micro 4x8 (cols packed; col split {tx*4, 128+tx*4})
// MODE 0: out = LN(A@B + res)            (res = x_in, LN=ln_agg)  -> g_h
// MODE 1: out = LN(A@B + bias + res)     (res = g_h,  LN=ln_out)  -> d_out
// =====================================================================
template<int KDIM, int MODE>
__global__ __launch_bounds__(256)
void gemmB(const float* __restrict__ A, const float* __restrict__ Bw,
           const float* __restrict__ res, const float* __restrict__ bias,
           const float* __restrict__ lg, const float* __restrict__ lb,
           float* __restrict__ C) {
    __shared__ float As[16][32];
    __shared__ float Bs[16][256];
    const int mBase = blockIdx.x * 32;
    const int tid = threadIdx.x;
    const int ty = tid >> 5, tx = tid & 31;   // warp == one ty (4 rows)

    float2 acc[4][4];
    #pragma unroll
    for (int i = 0; i < 4; i++)
        #pragma unroll
        for (int j = 0; j < 4; j++) acc[i][j] = make_float2(0.f, 0.f);

    const int lm = tid >> 3;            // 0..31
    const int lk = (tid & 7) * 2;       // 0..14
    const int bk = tid >> 4;            // 0..15
    const int bn = (tid & 15) * 16;

    for (int k0 = 0; k0 < KDIM; k0 += 16) {
        float2 av = *(const float2*)&A[(mBase + lm) * KDIM + k0 + lk];
        As[lk][lm] = av.x; As[lk + 1][lm] = av.y;
        #pragma unroll
        for (int c = 0; c < 4; c++)
            *(float4*)&Bs[bk][bn + c * 4] = *(const float4*)&Bw[(k0 + bk) * 256 + bn + c * 4];
        __syncthreads();
        #pragma unroll
        for (int k = 0; k < 16; k++) {
            float4 av4 = *(const float4*)&As[k][ty * 4];
            float2 ad[4] = { dup2(av4.x), dup2(av4.y), dup2(av4.z), dup2(av4.w) };
            float4 b0 = *(const float4*)&Bs[k][tx * 4];
            float4 b1 = *(const float4*)&Bs[k][128 + tx * 4];
            float2 bp[4];
            bp[0] = make_float2(b0.x, b0.y); bp[1] = make_float2(b0.z, b0.w);
            bp[2] = make_float2(b1.x, b1.y); bp[3] = make_float2(b1.z, b1.w);
            #pragma unroll
            for (int i = 0; i < 4; i++)
                #pragma unroll
                for (int j = 0; j < 4; j++) fma2(acc[i][j], ad[i], bp[j]);
        }
        __syncthreads();
    }

    // epilogue: unpack, add residual (+bias), LayerNorm per row, store
    float4 ba = make_float4(0.f, 0.f, 0.f, 0.f), bb4 = ba;
    if (MODE == 1) {
        ba  = *(const float4*)&bias[tx * 4];
        bb4 = *(const float4*)&bias[128 + tx * 4];
    }
    const float4 ga  = *(const float4*)&lg[tx * 4];
    const float4 gb  = *(const float4*)&lg[128 + tx * 4];
    const float4 oa  = *(const float4*)&lb[tx * 4];
    const float4 ob  = *(const float4*)&lb[128 + tx * 4];

    #pragma unroll
    for (int i = 0; i < 4; i++) {
        const int row = mBase + ty * 4 + i;
        float4 r0 = *(const float4*)&res[row * 256 + tx * 4];
        float4 r1 = *(const float4*)&res[row * 256 + 128 + tx * 4];
        float v[8];
        v[0] = acc[i][0].x + r0.x; v[1] = acc[i][0].y + r0.y;
        v[2] = acc[i][1].x + r0.z; v[3] = acc[i][1].y + r0.w;
        v[4] = acc[i][2].x + r1.x; v[5] = acc[i][2].y + r1.y;
        v[6] = acc[i][3].x + r1.z; v[7] = acc[i][3].y + r1.w;
        if (MODE == 1) {
            v[0] += ba.x;  v[1] += ba.y;  v[2] += ba.z;  v[3] += ba.w;
            v[4] += bb4.x; v[5] += bb4.y; v[6] += bb4.z; v[7] += bb4.w;
        }
        float s = 0.f, q = 0.f;
        #pragma unroll
        for (int c = 0; c < 8; c++) { s += v[c]; q += v[c] * v[c]; }
        #pragma unroll
        for (int o = 16; o > 0; o >>= 1) {
            s += __shfl_xor_sync(0xffffffffu, s, o);
            q += __shfl_xor_sync(0xffffffffu, q, o);
        }
        const float mean = s * (1.f / 256.f);
        const float var  = q * (1.f / 256.f) - mean * mean;
        const float rstd = rsqrtf(var + LNEPS);
        float4 o0, o1;
        o0.x = (v[0] - mean) * rstd * ga.x + oa.x;
        o0.y = (v[1] - mean) * rstd * ga.y + oa.y;
        o0.z = (v[2] - mean) * rstd * ga.z + oa.z;
        o0.w = (v[3] - mean) * rstd * ga.w + oa.w;
        o1.x = (v[4] - mean) * rstd * gb.x + ob.x;
        o1.y = (v[5] - mean) * rstd * gb.y + ob.y;
        o1.z = (v[6] - mean) * rstd * gb.z + ob.z;
        o1.w = (v[7] - mean) * rstd * gb.w + ob.w;
        *(float4*)&C[row * 256 + tx * 4] = o0;
        *(float4*)&C[row * 256 + 128 + tx * 4] = o1;
    }
}

// =====================================================================
// scores: S[b,h,l,i,j] = (1/sqrt(32)) * sum_d q[b,i,l,h,d] * k[b,l,j,h,d]
// one block per (b,h,l): 64x64x32 GEMM
// =====================================================================
__global__ __launch_bounds__(256)
void scores_kernel() {
    __shared__ float Qs[32][64];
    __shared__ float Ks[32][64];
    const int bid = blockIdx.x;
    const int l = bid & 63, h = (bid >> 6) & 7, b = bid >> 9;
    const int tid = threadIdx.x;

    const int r  = tid >> 2;          // 0..63
    const int dg = (tid & 3) * 8;
    {
        const float* qp = &g_q[(((b * NN + r) * NN + l) * EE) + h * DD + dg];
        float4 q0 = *(const float4*)qp; float4 q1 = *(const float4*)(qp + 4);
        Qs[dg+0][r] = q0.x; Qs[dg+1][r] = q0.y; Qs[dg+2][r] = q0.z; Qs[dg+3][r] = q0.w;
        Qs[dg+4][r] = q1.x; Qs[dg+5][r] = q1.y; Qs[dg+6][r] = q1.z; Qs[dg+7][r] = q1.w;
        const float* kp = &g_k[(((b * NN + l) * NN + r) * EE) + h * DD + dg];
        float4 k0 = *(const float4*)kp; float4 k1 = *(const float4*)(kp + 4);
        Ks[dg+0][r] = k0.x; Ks[dg+1][r] = k0.y; Ks[dg+2][r] = k0.z; Ks[dg+3][r] = k0.w;
        Ks[dg+4][r] = k1.x; Ks[dg+5][r] = k1.y; Ks[dg+6][r] = k1.z; Ks[dg+7][r] = k1.w;
    }
    __syncthreads();

    const int ty = tid >> 4, tx = tid & 15;
    float acc[4][4];
    #pragma unroll
    for (int i = 0; i < 4; i++)
        #pragma unroll
        for (int j = 0; j < 4; j++) acc[i][j] = 0.f;

    #pragma unroll
    for (int d = 0; d < 32; d++) {
        float4 a  = *(const float4*)&Qs[d][ty * 4];
        float4 bv = *(const float4*)&Ks[d][tx * 4];
        float aa[4] = { a.x, a.y, a.z, a.w };
        float bbv[4] = { bv.x, bv.y, bv.z, bv.w };
        #pragma unroll
        for (int i = 0; i < 4; i++)
            #pragma unroll
            for (int j = 0; j < 4; j++) acc[i][j] = fmaf(aa[i], bbv[j], acc[i][j]);
    }
    const float sc = 0.17677669529663687f;  // 1/sqrt(32)
    float* sp = &g_att[((b * HH + h) * NN + l) * NN * NN];
    #pragma unroll
    for (int i = 0; i < 4; i++) {
        float4 v = make_float4(acc[i][0] * sc, acc[i][1] * sc, acc[i][2] * sc, acc[i][3] * sc);
        *(float4*)&sp[(ty * 4 + i) * 64 + tx * 4] = v;
    }
}

// =====================================================================
// softmax over l (axis 2): one thread per (b,h,i,j)
// =====================================================================
__global__ __launch_bounds__(256)
void softmax_kernel() {
    const int t = blockIdx.x * 256 + threadIdx.x;   // 65536 total
    const int j = t & 63, i = (t >> 6) & 63, bh = t >> 12;
    float* base = &g_att[bh * 262144 + i * 64 + j];
    float r[64];
    float mx = -1e30f;
    #pragma unroll
    for (int l = 0; l < 64; l++) { r[l] = base[l * 4096]; mx = fmaxf(mx, r[l]); }
    float s = 0.f;
    #pragma unroll
    for (int l = 0; l < 64; l++) { r[l] = expf(r[l] - mx); s += r[l]; }
    const float inv = 1.f / s;
    #pragma unroll
    for (int l = 0; l < 64; l++) base[l * 4096] = r[l] * inv;
}

// =====================================================================
// aggregate: out[b,i,j,h,d] = sum_l att[b,h,l,i,j]*v1[b,i,l,h,d]*v2[b,l,j,h,d]
// one block per (b,h, i-tile of 8); thread = (i', d); 64 j-accumulators
// =====================================================================
__global__ __launch_bounds__(256)
void aggregate_kernel() {
    __shared__ float att_s[8][64];
    __shared__ float v2s[64][36];   // padded to break store bank conflicts
    const int bid = blockIdx.x;     // 128 blocks
    const int it = bid & 7, h = (bid >> 3) & 7, b = bid >> 6;
    const int iBase = it * 8;
    const int tid = threadIdx.x;
    const int ip = tid >> 5, d = tid & 31;

    float acc[64];
    #pragma unroll
    for (int j = 0; j < 64; j++) acc[j] = 0.f;

    const int aj = (tid * 2) & 63, ai = (tid * 2) >> 6;
    const int vj = tid >> 2, vdg = (tid & 3) * 8;

    for (int l = 0; l < 64; l++) {
        const float v1v = g_v1[(((b * NN + iBase + ip) * NN + l) * EE) + h * DD + d];
        *(float2*)&att_s[ai][aj] =
            *(const float2*)&g_att[(b * HH + h) * 262144 + l * 4096 + (iBase + ai) * 64 + aj];
        const float* vp = &g_v2[(((b * NN + l) * NN + vj) * EE) + h * DD + vdg];
        *(float4*)&v2s[vj][vdg]     = *(const float4*)vp;
        *(float4*)&v2s[vj][vdg + 4] = *(const float4*)(vp + 4);
        __syncthreads();
        #pragma unroll
        for (int j4 = 0; j4 < 64; j4 += 4) {
            float4 a = *(const float4*)&att_s[ip][j4];
            acc[j4+0] = fmaf(a.x * v1v, v2s[j4+0][d], acc[j4+0]);
            acc[j4+1] = fmaf(a.y * v1v, v2s[j4+1][d], acc[j4+1]);
            acc[j4+2] = fmaf(a.z * v1v, v2s[j4+2][d], acc[j4+2]);
            acc[j4+3] = fmaf(a.w * v1v, v2s[j4+3][d], acc[j4+3]);
        }
        __syncthreads();
    }
    #pragma unroll
    for (int j = 0; j < 64; j++)
        g_ao[(((b * NN + iBase + ip) * NN + j) * EE) + h * DD + d] = acc[j];
}

// =====================================================================
extern "C" void kernel_launch(void* const* d_in, const int* in_sizes, int n_in,
                              void* d_out, int out_size) {
    const float* x    = (const float*)d_in[0];
    const float* Wq   = (const float*)d_in[1];
    const float* Wk   = (const float*)d_in[2];
    const float* Wv1  = (const float*)d_in[3];
    const float* Wv2  = (const float*)d_in[4];
    const float* Wo   = (const float*)d_in[5];
    const float* lag  = (const float*)d_in[6];
    const float* lab  = (const float*)d_in[7];
    const float* W1   = (const float*)d_in[8];
    const float* b1   = (const float*)d_in[9];
    const float* W2   = (const float*)d_in[10];
    const float* b2   = (const float*)d_in[11];
    const float* log_ = (const float*)d_in[12];
    const float* lob  = (const float*)d_in[13];

    float *pq, *pk, *pv1, *pv2, *pao, *ph, *pm1;
    cudaGetSymbolAddress((void**)&pq,  g_q);
    cudaGetSymbolAddress((void**)&pk,  g_k);
    cudaGetSymbolAddress((void**)&pv1, g_v1);
    cudaGetSymbolAddress((void**)&pv2, g_v2);
    cudaGetSymbolAddress((void**)&pao, g_ao);
    cudaGetSymbolAddress((void**)&ph,  g_h);
    cudaGetSymbolAddress((void**)&pm1, g_m1);

    dim3 gQ(64, 4);
    gemmA<256, 256, false><<<gQ, 256>>>(x, Wq,  nullptr, pq);
    gemmA<256, 256, false><<<gQ, 256>>>(x, Wk,  nullptr, pk);
    gemmA<256, 256, false><<<gQ, 256>>>(x, Wv1, nullptr, pv1);
    gemmA<256, 256, false><<<gQ, 256>>>(x, Wv2, nullptr, pv2);

    scores_kernel<<<1024, 256>>>();
    softmax_kernel<<<256, 256>>>();
    aggregate_kernel<<<128, 256>>>();

    gemmB<256, 0><<<256, 256>>>(pao, Wo, x, nullptr, lag, lab, ph);
    gemmA<256, 512, true><<<dim3(64, 8), 256>>>(ph, W1, b1, pm1);
    gemmB<512, 1><<<256, 256>>>(pm1, W2, ph, b2, log_, lob, (float*)d_out);
}

// round 4
// speedup vs baseline: 1.5384x; 1.5379x over previous
#include <cuda_runtime.h>
#include <cuda_bf16.h>
#include <math.h>
#include <stdint.h>

#define BB 2
#define NN 64
#define EE 256
#define HH 8
#define DD 32
#define FF 512
#define MR 8192
#define LNEPS 1e-5f

// ---------------- scratch ----------------
__device__ float g_q [MR*EE];
__device__ float g_k [MR*EE];
__device__ float g_v1[MR*EE];
__device__ float g_v2[MR*EE];
__device__ float g_att[BB*HH*NN*NN*NN];   // [b,h,l,i,j]
__device__ float g_h [MR*EE];             // post LN1 plain fp32
__device__ __nv_bfloat16 g_x2 [MR*512];   // x split [row][hi256|lo256]
__device__ __nv_bfloat16 g_ao2[MR*512];   // attn-out split
__device__ __nv_bfloat16 g_h2 [MR*512];   // post LN1 split
__device__ __nv_bfloat16 g_m12[(size_t)MR*1024]; // relu(h@W1+b1) split [row][hi512|lo512]
__device__ __nv_bfloat16 g_wqkv2[1024*512];      // [n][hi256|lo256], concat q,k,v1,v2
__device__ __nv_bfloat16 g_wot2 [256*512];
__device__ __nv_bfloat16 g_w1t2 [512*512];
__device__ __nv_bfloat16 g_w2t2 [256*1024];

// ---------------- helpers ----------------
__device__ __forceinline__ uint32_t s2u(const void* p) {
    uint32_t a;
    asm("{ .reg .u64 t; cvta.to.shared.u64 t, %1; cvt.u32.u64 %0, t; }" : "=r"(a) : "l"(p));
    return a;
}
__device__ __forceinline__ void ldsm4(uint32_t* r, uint32_t a) {
    asm volatile("ldmatrix.sync.aligned.m8n8.x4.shared.b16 {%0,%1,%2,%3}, [%4];"
        : "=r"(r[0]), "=r"(r[1]), "=r"(r[2]), "=r"(r[3]) : "r"(a));
}
__device__ __forceinline__ void mma16816(float* c, const uint32_t* a, const uint32_t* b) {
    asm volatile("mma.sync.aligned.m16n8k16.row.col.f32.bf16.bf16.f32 "
        "{%0,%1,%2,%3}, {%4,%5,%6,%7}, {%8,%9}, {%0,%1,%2,%3};"
        : "+f"(c[0]), "+f"(c[1]), "+f"(c[2]), "+f"(c[3])
        : "r"(a[0]), "r"(a[1]), "r"(a[2]), "r"(a[3]), "r"(b[0]), "r"(b[1]));
}
__device__ __forceinline__ void bfsplit(float v, __nv_bfloat16& h, __nv_bfloat16& l) {
    h = __float2bfloat16_rn(v);
    l = __float2bfloat16_rn(v - __bfloat162float(h));
}

// ---------------- prep kernels ----------------
// W [K][N] row-major -> out [n][2K] bf16 (hi 0..K, lo K..2K)
__global__ void prep_w(const float* __restrict__ W, __nv_bfloat16* __restrict__ out, int K, int N) {
    int t = blockIdx.x * 256 + threadIdx.x;
    if (t >= K * N) return;
    int n = t / K, k = t - n * K;
    float v = W[k * N + n];
    __nv_bfloat16 h, l; bfsplit(v, h, l);
    out[(size_t)n * 2 * K + k] = h;
    out[(size_t)n * 2 * K + K + k] = l;
}
__global__ void split_x(const float* __restrict__ x) {
    int t = blockIdx.x * 256 + threadIdx.x;
    int row = t >> 8, c = t & 255;
    float v = x[t];
    __nv_bfloat16 h, l; bfsplit(v, h, l);
    g_x2[(size_t)row * 512 + c] = h;
    g_x2[(size_t)row * 512 + 256 + c] = l;
}

// =====================================================================
// bf16 split-precision mma.sync GEMM. 256 thr, 8 warps, warp tile 32x64.
// MODE 0: QKV scatter (o0,o1v,o2,o3 fp32)     [BM=128,BN=128, grid y=8]
// MODE 1: relu(D+bias) -> o1v bf16 split m12  [BM=128,BN=128, grid y=4]
// MODE 2: LN(D+res) -> o0 fp32 h, o1v bf16 split h2 [BM=64,BN=256]
// MODE 3: LN(D+bias+res) -> o0 fp32 (d_out)        [BM=64,BN=256]
// =====================================================================
template<int BM, int BN, int KDIM, int MODE>
__global__ void __launch_bounds__(256)
gemm_mma(const __nv_bfloat16* __restrict__ A2, const __nv_bfloat16* __restrict__ B2,
         const float* __restrict__ res, const float* __restrict__ bias,
         const float* __restrict__ lg, const float* __restrict__ lb,
         float* __restrict__ o0, void* __restrict__ o1v,
         float* __restrict__ o2, float* __restrict__ o3)
{
    constexpr int K2 = 2 * KDIM, C = KDIM / 32;
    constexpr int WR = BM / 32;
    constexpr int AH = 0, AL = BM * 40, BH = 2 * BM * 40, BL = 2 * BM * 40 + BN * 40;
    extern __shared__ __nv_bfloat16 sm[];
    const int tid = threadIdx.x, wid = tid >> 5, lane = tid & 31;
    const int mBase = blockIdx.x * BM, nBase = blockIdx.y * BN;
    const int wrB = (wid % WR) * 32, wcB = (wid / WR) * 64;
    const uint32_t smu = s2u(sm);

    float acc[2][8][4];
    #pragma unroll
    for (int i = 0; i < 2; i++)
        #pragma unroll
        for (int j = 0; j < 8; j++)
            #pragma unroll
            for (int v = 0; v < 4; v++) acc[i][j][v] = 0.f;

    // ldmatrix lane address components
    const int aRow = lane & 15, aK = ((lane >> 4) & 1) * 8;
    const int bN = ((lane >> 4) & 1) * 8 + (lane & 7), bK = ((lane >> 3) & 1) * 8;

    for (int c = 0; c < C; c++) {
        const int ca = c * 32;
        #pragma unroll
        for (int s = 0; s < 2; s++) {
            #pragma unroll
            for (int i = 0; i < BM * 4 / 256; i++) {
                int f = tid + 256 * i; int r = f >> 2, c8 = (f & 3) * 8;
                uint4 v = *(const uint4*)&A2[(size_t)(mBase + r) * K2 + s * KDIM + ca + c8];
                int o = (s ? AL : AH) + r * 40 + c8;
                *(uint2*)&sm[o]     = make_uint2(v.x, v.y);
                *(uint2*)&sm[o + 4] = make_uint2(v.z, v.w);
            }
            #pragma unroll
            for (int i = 0; i < BN * 4 / 256; i++) {
                int f = tid + 256 * i; int r = f >> 2, c8 = (f & 3) * 8;
                uint4 v = *(const uint4*)&B2[(size_t)(nBase + r) * K2 + s * KDIM + ca + c8];
                int o = (s ? BL : BH) + r * 40 + c8;
                *(uint2*)&sm[o]     = make_uint2(v.x, v.y);
                *(uint2*)&sm[o + 4] = make_uint2(v.z, v.w);
            }
        }
        __syncthreads();
        #pragma unroll
        for (int k16 = 0; k16 < 2; k16++) {
            const int k0 = k16 * 16;
            uint32_t ah[2][4], al_[2][4], bh[8][2], bl_[8][2];
            #pragma unroll
            for (int mr = 0; mr < 2; mr++) {
                ldsm4(ah[mr],  smu + 2u * (AH + (wrB + mr * 16 + aRow) * 40 + k0 + aK));
                ldsm4(al_[mr], smu + 2u * (AL + (wrB + mr * 16 + aRow) * 40 + k0 + aK));
            }
            #pragma unroll
            for (int np = 0; np < 4; np++) {
                uint32_t r4[4];
                ldsm4(r4, smu + 2u * (BH + (wcB + np * 16 + bN) * 40 + k0 + bK));
                bh[2*np][0] = r4[0]; bh[2*np][1] = r4[1];
                bh[2*np+1][0] = r4[2]; bh[2*np+1][1] = r4[3];
                ldsm4(r4, smu + 2u * (BL + (wcB + np * 16 + bN) * 40 + k0 + bK));
                bl_[2*np][0] = r4[0]; bl_[2*np][1] = r4[1];
                bl_[2*np+1][0] = r4[2]; bl_[2*np+1][1] = r4[3];
            }
            #pragma unroll
            for (int mr = 0; mr < 2; mr++)
                #pragma unroll
                for (int nc = 0; nc < 8; nc++) mma16816(acc[mr][nc], ah[mr], bh[nc]);
            #pragma unroll
            for (int mr = 0; mr < 2; mr++)
                #pragma unroll
                for (int nc = 0; nc < 8; nc++) mma16816(acc[mr][nc], ah[mr], bl_[nc]);
            #pragma unroll
            for (int mr = 0; mr < 2; mr++)
                #pragma unroll
                for (int nc = 0; nc < 8; nc++) mma16816(acc[mr][nc], al_[mr], bh[nc]);
        }
        __syncthreads();
    }

    const int lR = lane >> 2, lC = (lane & 3) * 2;
    if constexpr (MODE == 0) {
        const int sel = blockIdx.y >> 1;
        float* qout = sel == 0 ? o0 : sel == 1 ? (float*)o1v : sel == 2 ? o2 : o3;
        const int colBase = (blockIdx.y & 1) * 128 + wcB;
        #pragma unroll
        for (int mr = 0; mr < 2; mr++)
            #pragma unroll
            for (int nc = 0; nc < 8; nc++) {
                int row = mBase + wrB + mr * 16 + lR;
                int col = colBase + nc * 8 + lC;
                *(float2*)&qout[(size_t)row * 256 + col] = make_float2(acc[mr][nc][0], acc[mr][nc][1]);
                *(float2*)&qout[(size_t)(row + 8) * 256 + col] = make_float2(acc[mr][nc][2], acc[mr][nc][3]);
            }
    } else if constexpr (MODE == 1) {
        __nv_bfloat16* out = (__nv_bfloat16*)o1v;
        #pragma unroll
        for (int mr = 0; mr < 2; mr++)
            #pragma unroll
            for (int nc = 0; nc < 8; nc++) {
                int row = mBase + wrB + mr * 16 + lR;
                int colG = nBase + wcB + nc * 8 + lC;
                float b0 = bias[colG], b1 = bias[colG + 1];
                #pragma unroll
                for (int s = 0; s < 2; s++) {
                    int rr = row + s * 8;
                    float v0 = fmaxf(acc[mr][nc][2*s] + b0, 0.f);
                    float v1 = fmaxf(acc[mr][nc][2*s+1] + b1, 0.f);
                    __nv_bfloat162 hv, lv;
                    bfsplit(v0, hv.x, lv.x); bfsplit(v1, hv.y, lv.y);
                    *(__nv_bfloat162*)&out[(size_t)rr * 1024 + colG] = hv;
                    *(__nv_bfloat162*)&out[(size_t)rr * 1024 + 512 + colG] = lv;
                }
            }
    } else {
        float* stage = (float*)sm;   // [64][264]
        #pragma unroll
        for (int mr = 0; mr < 2; mr++)
            #pragma unroll
            for (int nc = 0; nc < 8; nc++) {
                int rowL = wrB + mr * 16 + lR;
                int col = wcB + nc * 8 + lC;
                *(float2*)&stage[rowL * 264 + col] = make_float2(acc[mr][nc][0], acc[mr][nc][1]);
                *(float2*)&stage[(rowL + 8) * 264 + col] = make_float2(acc[mr][nc][2], acc[mr][nc][3]);
            }
        __syncthreads();
        const int r = tid >> 2, q = tid & 3;
        const size_t grow = mBase + r;
        float sum = 0.f, sq = 0.f;
        #pragma unroll
        for (int c4 = 0; c4 < 16; c4++) {
            int cc = q * 64 + c4 * 4;
            float4 v = *(float4*)&stage[r * 264 + cc];
            float4 rv = *(const float4*)&res[grow * 256 + cc];
            v.x += rv.x; v.y += rv.y; v.z += rv.z; v.w += rv.w;
            if constexpr (MODE == 3) {
                float4 bv = *(const float4*)&bias[cc];
                v.x += bv.x; v.y += bv.y; v.z += bv.z; v.w += bv.w;
            }
            *(float4*)&stage[r * 264 + cc] = v;
            sum += v.x + v.y + v.z + v.w;
            sq  += v.x * v.x + v.y * v.y + v.z * v.z + v.w * v.w;
        }
        sum += __shfl_xor_sync(0xffffffffu, sum, 1);
        sum += __shfl_xor_sync(0xffffffffu, sum, 2);
        sq  += __shfl_xor_sync(0xffffffffu, sq, 1);
        sq  += __shfl_xor_sync(0xffffffffu, sq, 2);
        const float mean = sum * (1.f / 256.f);
        const float var  = sq * (1.f / 256.f) - mean * mean;
        const float rs   = rsqrtf(var + LNEPS);
        __nv_bfloat16* h2o = (__nv_bfloat16*)o1v;
        #pragma unroll
        for (int c4 = 0; c4 < 16; c4++) {
            int cc = q * 64 + c4 * 4;
            float4 v = *(float4*)&stage[r * 264 + cc];
            float4 g4 = *(const float4*)&lg[cc];
            float4 b4 = *(const float4*)&lb[cc];
            float4 y;
            y.x = (v.x - mean) * rs * g4.x + b4.x;
            y.y = (v.y - mean) * rs * g4.y + b4.y;
            y.z = (v.z - mean) * rs * g4.z + b4.z;
            y.w = (v.w - mean) * rs * g4.w + b4.w;
            *(float4*)&o0[grow * 256 + cc] = y;
            if constexpr (MODE == 2) {
                __nv_bfloat162 h01, l01, h23, l23;
                bfsplit(y.x, h01.x, l01.x); bfsplit(y.y, h01.y, l01.y);
                bfsplit(y.z, h23.x, l23.x); bfsplit(y.w, h23.y, l23.y);
                *(__nv_bfloat162*)&h2o[grow * 512 + cc]       = h01;
                *(__nv_bfloat162*)&h2o[grow * 512 + cc + 2]   = h23;
                *(__nv_bfloat162*)&h2o[grow * 512 + 256 + cc]     = l01;
                *(__nv_bfloat162*)&h2o[grow * 512 + 256 + cc + 2] = l23;
            }
        }
    }
}

// =====================================================================
// scores: one block per (b,h,l): 64x64x32
// =====================================================================
__global__ __launch_bounds__(256)
void scores_kernel() {
    __shared__ float Qs[32][64];
    __shared__ float Ks[32][64];
    const int bid = blockIdx.x;
    const int l = bid & 63, h = (bid >> 6) & 7, b = bid >> 9;
    const int tid = threadIdx.x;
    const int r  = tid >> 2;
    const int dg = (tid & 3) * 8;
    {
        const float* qp = &g_q[(((b * NN + r) * NN + l) * EE) + h * DD + dg];
        float4 q0 = *(const float4*)qp; float4 q1 = *(const float4*)(qp + 4);
        Qs[dg+0][r] = q0.x; Qs[dg+1][r] = q0.y; Qs[dg+2][r] = q0.z; Qs[dg+3][r] = q0.w;
        Qs[dg+4][r] = q1.x; Qs[dg+5][r] = q1.y; Qs[dg+6][r] = q1.z; Qs[dg+7][r] = q1.w;
        const float* kp = &g_k[(((b * NN + l) * NN + r) * EE) + h * DD + dg];
        float4 k0 = *(const float4*)kp; float4 k1 = *(const float4*)(kp + 4);
        Ks[dg+0][r] = k0.x; Ks[dg+1][r] = k0.y; Ks[dg+2][r] = k0.z; Ks[dg+3][r] = k0.w;
        Ks[dg+4][r] = k1.x; Ks[dg+5][r] = k1.y; Ks[dg+6][r] = k1.z; Ks[dg+7][r] = k1.w;
    }
    __syncthreads();
    const int ty = tid >> 4, tx = tid & 15;
    float acc[4][4];
    #pragma unroll
    for (int i = 0; i < 4; i++)
        #pragma unroll
        for (int j = 0; j < 4; j++) acc[i][j] = 0.f;
    #pragma unroll
    for (int d = 0; d < 32; d++) {
        float4 a  = *(const float4*)&Qs[d][ty * 4];
        float4 bv = *(const float4*)&Ks[d][tx * 4];
        float aa[4] = { a.x, a.y, a.z, a.w };
        float bb[4] = { bv.x, bv.y, bv.z, bv.w };
        #pragma unroll
        for (int i = 0; i < 4; i++)
            #pragma unroll
            for (int j = 0; j < 4; j++) acc[i][j] = fmaf(aa[i], bb[j], acc[i][j]);
    }
    const float sc = 0.17677669529663687f;
    float* sp = &g_att[((b * HH + h) * NN + l) * NN * NN];
    #pragma unroll
    for (int i = 0; i < 4; i++) {
        float4 v = make_float4(acc[i][0]*sc, acc[i][1]*sc, acc[i][2]*sc, acc[i][3]*sc);
        *(float4*)&sp[(ty * 4 + i) * 64 + tx * 4] = v;
    }
}

// softmax over l
__global__ __launch_bounds__(256)
void softmax_kernel() {
    const int t = blockIdx.x * 256 + threadIdx.x;
    const int j = t & 63, i = (t >> 6) & 63, bh = t >> 12;
    float* base = &g_att[bh * 262144 + i * 64 + j];
    float r[64];
    float mx = -1e30f;
    #pragma unroll
    for (int l = 0; l < 64; l++) { r[l] = base[l * 4096]; mx = fmaxf(mx, r[l]); }
    float s = 0.f;
    #pragma unroll
    for (int l = 0; l < 64; l++) { r[l] = expf(r[l] - mx); s += r[l]; }
    const float inv = 1.f / s;
    #pragma unroll
    for (int l = 0; l < 64; l++) base[l * 4096] = r[l] * inv;
}

// aggregate -> split bf16 output g_ao2
__global__ __launch_bounds__(256)
void aggregate_kernel() {
    __shared__ float att_s[8][64];
    __shared__ float v2s[64][36];
    const int bid = blockIdx.x;
    const int it = bid & 7, hh = (bid >> 3) & 7, b = bid >> 6;
    const int iBase = it * 8;
    const int tid = threadIdx.x;
    const int ip = tid >> 5, d = tid & 31;
    float acc[64];
    #pragma unroll
    for (int j = 0; j < 64; j++) acc[j] = 0.f;
    const int aj = (tid * 2) & 63, ai = (tid * 2) >> 6;
    const int vj = tid >> 2, vdg = (tid & 3) * 8;
    for (int l = 0; l < 64; l++) {
        const float v1v = g_v1[(((b * NN + iBase + ip) * NN + l) * EE) + hh * DD + d];
        *(float2*)&att_s[ai][aj] =
            *(const float2*)&g_att[(b * HH + hh) * 262144 + l * 4096 + (iBase + ai) * 64 + aj];
        const float* vp = &g_v2[(((b * NN + l) * NN + vj) * EE) + hh * DD + vdg];
        *(float4*)&v2s[vj][vdg]     = *(const float4*)vp;
        *(float4*)&v2s[vj][vdg + 4] = *(const float4*)(vp + 4);
        __syncthreads();
        #pragma unroll
        for (int j4 = 0; j4 < 64; j4 += 4) {
            float4 a = *(const float4*)&att_s[ip][j4];
            acc[j4+0] = fmaf(a.x * v1v, v2s[j4+0][d], acc[j4+0]);
            acc[j4+1] = fmaf(a.y * v1v, v2s[j4+1][d], acc[j4+1]);
            acc[j4+2] = fmaf(a.z * v1v, v2s[j4+2][d], acc[j4+2]);
            acc[j4+3] = fmaf(a.w * v1v, v2s[j4+3][d], acc[j4+3]);
        }
        __syncthreads();
    }
    #pragma unroll
    for (int j = 0; j < 64; j++) {
        const size_t row = ((size_t)(b * NN + iBase + ip) * NN + j);
        __nv_bfloat16 h, l; bfsplit(acc[j], h, l);
        g_ao2[row * 512 + hh * DD + d] = h;
        g_ao2[row * 512 + 256 + hh * DD + d] = l;
    }
}

// =====================================================================
extern "C" void kernel_launch(void* const* d_in, const int* in_sizes, int n_in,
                              void* d_out, int out_size) {
    const float* x    = (const float*)d_in[0];
    const float* Wq   = (const float*)d_in[1];
    const float* Wk   = (const float*)d_in[2];
    const float* Wv1  = (const float*)d_in[3];
    const float* Wv2  = (const float*)d_in[4];
    const float* Wo   = (const float*)d_in[5];
    const float* lag  = (const float*)d_in[6];
    const float* lab  = (const float*)d_in[7];
    const float* W1   = (const float*)d_in[8];
    const float* b1   = (const float*)d_in[9];
    const float* W2   = (const float*)d_in[10];
    const float* b2   = (const float*)d_in[11];
    const float* log_ = (const float*)d_in[12];
    const float* lob  = (const float*)d_in[13];

    float *pq, *pk, *pv1, *pv2, *ph;
    __nv_bfloat16 *px2, *pao2, *ph2, *pm12, *pwqkv, *pwot, *pw1t, *pw2t;
    cudaGetSymbolAddress((void**)&pq,  g_q);
    cudaGetSymbolAddress((void**)&pk,  g_k);
    cudaGetSymbolAddress((void**)&pv1, g_v1);
    cudaGetSymbolAddress((void**)&pv2, g_v2);
    cudaGetSymbolAddress((void**)&ph,  g_h);
    cudaGetSymbolAddress((void**)&px2, g_x2);
    cudaGetSymbolAddress((void**)&pao2, g_ao2);
    cudaGetSymbolAddress((void**)&ph2, g_h2);
    cudaGetSymbolAddress((void**)&pm12, g_m12);
    cudaGetSymbolAddress((void**)&pwqkv, g_wqkv2);
    cudaGetSymbolAddress((void**)&pwot, g_wot2);
    cudaGetSymbolAddress((void**)&pw1t, g_w1t2);
    cudaGetSymbolAddress((void**)&pw2t, g_w2t2);

    static int attr_done = 0;
    (void)attr_done;
    cudaFuncSetAttribute(gemm_mma<128,128,256,0>, cudaFuncAttributeMaxDynamicSharedMemorySize, 40960);
    cudaFuncSetAttribute(gemm_mma<128,128,256,1>, cudaFuncAttributeMaxDynamicSharedMemorySize, 40960);
    cudaFuncSetAttribute(gemm_mma<64,256,256,2>,  cudaFuncAttributeMaxDynamicSharedMemorySize, 67584);
    cudaFuncSetAttribute(gemm_mma<64,256,512,3>,  cudaFuncAttributeMaxDynamicSharedMemorySize, 67584);

    split_x<<<MR, 256>>>(x);
    prep_w<<<256, 256>>>(Wq,  pwqkv,             256, 256);
    prep_w<<<256, 256>>>(Wk,  pwqkv + 256 * 512, 256, 256);
    prep_w<<<256, 256>>>(Wv1, pwqkv + 512 * 512, 256, 256);
    prep_w<<<256, 256>>>(Wv2, pwqkv + 768 * 512, 256, 256);
    prep_w<<<256, 256>>>(Wo,  pwot,              256, 256);
    prep_w<<<512, 256>>>(W1,  pw1t,              256, 512);
    prep_w<<<512, 256>>>(W2,  pw2t,              512, 256);

    gemm_mma<128,128,256,0><<<dim3(64, 8), 256, 40960>>>(px2, pwqkv,
        nullptr, nullptr, nullptr, nullptr, pq, pk, pv1, pv2);

    scores_kernel<<<1024, 256>>>();
    softmax_kernel<<<256, 256>>>();
    aggregate_kernel<<<128, 256>>>();

    gemm_mma<64,256,256,2><<<dim3(128, 1), 256, 67584>>>(pao2, pwot,
        x, nullptr, lag, lab, ph, ph2, nullptr, nullptr);
    gemm_mma<128,128,256,1><<<dim3(64, 4), 256, 40960>>>(ph2, pw1t,
        nullptr, b1, nullptr, nullptr, nullptr, pm12, nullptr, nullptr);
    gemm_mma<64,256,512,3><<<dim3(128, 1), 256, 67584>>>(pm12, pw2t,
        ph, b2, log_, lob, (float*)d_out, nullptr, nullptr, nullptr);
}